// round 3
// baseline (speedup 1.0000x reference)
#include <cuda_runtime.h>
#include <cuda_bf16.h>
#include <cstdint>

#define D_MODEL 1024
#define N_HEADS 16
#define HEAD_DIM 64
#define BATCH 4
#define SEQ 2048
#define M_TOTAL (BATCH * SEQ)  // 8192

// ---------------------------------------------------------------------------
// Scratch (__device__ globals; no allocation allowed)
// ---------------------------------------------------------------------------
__device__ float g_Q[(size_t)BATCH * N_HEADS * SEQ * HEAD_DIM];  // [B,H,S,D] fp32
__device__ float g_K[(size_t)BATCH * N_HEADS * SEQ * HEAD_DIM];
__device__ float g_V[(size_t)BATCH * N_HEADS * SEQ * HEAD_DIM];
__device__ float g_O[(size_t)M_TOTAL * D_MODEL];                 // attn out fp32

// bf16 split scratch
__device__ __nv_bfloat16 s_qh[(size_t)M_TOTAL * D_MODEL];
__device__ __nv_bfloat16 s_ql[(size_t)M_TOTAL * D_MODEL];
__device__ __nv_bfloat16 s_kh[(size_t)M_TOTAL * D_MODEL];
__device__ __nv_bfloat16 s_kl[(size_t)M_TOTAL * D_MODEL];
__device__ __nv_bfloat16 s_vh[(size_t)M_TOTAL * D_MODEL];
__device__ __nv_bfloat16 s_vl[(size_t)M_TOTAL * D_MODEL];
__device__ __nv_bfloat16 s_oh[(size_t)M_TOTAL * D_MODEL];
__device__ __nv_bfloat16 s_ol[(size_t)M_TOTAL * D_MODEL];
__device__ __nv_bfloat16 s_wqh[(size_t)D_MODEL * D_MODEL];
__device__ __nv_bfloat16 s_wql[(size_t)D_MODEL * D_MODEL];
__device__ __nv_bfloat16 s_wkh[(size_t)D_MODEL * D_MODEL];
__device__ __nv_bfloat16 s_wkl[(size_t)D_MODEL * D_MODEL];
__device__ __nv_bfloat16 s_wvh[(size_t)D_MODEL * D_MODEL];
__device__ __nv_bfloat16 s_wvl[(size_t)D_MODEL * D_MODEL];
__device__ __nv_bfloat16 s_woh[(size_t)D_MODEL * D_MODEL];
__device__ __nv_bfloat16 s_wol[(size_t)D_MODEL * D_MODEL];

// ---------------------------------------------------------------------------
// Helpers (baseline PTX ISA only — no 'a'-suffix features)
// ---------------------------------------------------------------------------
__device__ __forceinline__ uint32_t smem_to_u32(const void* p) {
    uint32_t a;
    asm("{ .reg .u64 t; cvta.to.shared.u64 t, %1; cvt.u32.u64 %0, t; }" : "=r"(a) : "l"(p));
    return a;
}

#define CP_ASYNC16(dst, src) \
    asm volatile("cp.async.cg.shared.global [%0], [%1], 16;\n" :: "r"(dst), "l"(src))
#define CP_COMMIT() asm volatile("cp.async.commit_group;" ::: "memory")
#define CP_WAIT2()  asm volatile("cp.async.wait_group 2;" ::: "memory")

// d += a * b  (m16n8k16, bf16 in, f32 accum)
#define MMA16816(d, a, b) \
    asm volatile("mma.sync.aligned.m16n8k16.row.col.f32.bf16.bf16.f32 " \
        "{%0,%1,%2,%3}, {%4,%5,%6,%7}, {%8,%9}, {%0,%1,%2,%3};" \
        : "+f"((d)[0]), "+f"((d)[1]), "+f"((d)[2]), "+f"((d)[3]) \
        : "r"((a)[0]), "r"((a)[1]), "r"((a)[2]), "r"((a)[3]), \
          "r"((b)[0]), "r"((b)[1]))

// ---------------------------------------------------------------------------
// fp32 -> (bf16 hi, bf16 lo) split
// ---------------------------------------------------------------------------
__global__ void __launch_bounds__(256) cvt_split(
    const float4* __restrict__ x,
    __nv_bfloat162* __restrict__ hi,
    __nv_bfloat162* __restrict__ lo,
    int n4)
{
    int i = blockIdx.x * 256 + threadIdx.x;
    if (i >= n4) return;
    float4 v = x[i];
    __nv_bfloat16 h0 = __float2bfloat16(v.x);
    __nv_bfloat16 h1 = __float2bfloat16(v.y);
    __nv_bfloat16 h2 = __float2bfloat16(v.z);
    __nv_bfloat16 h3 = __float2bfloat16(v.w);
    __nv_bfloat16 l0 = __float2bfloat16(v.x - __bfloat162float(h0));
    __nv_bfloat16 l1 = __float2bfloat16(v.y - __bfloat162float(h1));
    __nv_bfloat16 l2 = __float2bfloat16(v.z - __bfloat162float(h2));
    __nv_bfloat16 l3 = __float2bfloat16(v.w - __bfloat162float(h3));
    hi[i * 2 + 0] = __halves2bfloat162(h0, h1);
    hi[i * 2 + 1] = __halves2bfloat162(h2, h3);
    lo[i * 2 + 0] = __halves2bfloat162(l0, l1);
    lo[i * 2 + 1] = __halves2bfloat162(l2, l3);
}

// ---------------------------------------------------------------------------
// mma.sync split-bf16 GEMM: C[8192,1024] = A[8192,1024]*B[1024,1024]^T + bias
// D = Ah*Bh + Al*Bh + Ah*Bl, fp32 accum.
// ---------------------------------------------------------------------------
#define ROW_B 80
#define TILE_SM (128 * ROW_B)     // 10240 B
#define STAGE_SM (4 * TILE_SM)    // 40960 B (Ah, Al, Bh, Bl)
#define NSTAGE 3
#define GEMM_SMEM (NSTAGE * STAGE_SM)  // 122880 B
#define NCHUNK 32                 // 1024 / 32

__device__ __forceinline__ void load_stage(
    char* smem, int s, int j, int tid,
    const __nv_bfloat16* ah, const __nv_bfloat16* al,
    const __nv_bfloat16* bh, const __nv_bfloat16* bl,
    int m0, int n0)
{
    const __nv_bfloat16* bases[4];
    bases[0] = ah + (size_t)m0 * D_MODEL;
    bases[1] = al + (size_t)m0 * D_MODEL;
    bases[2] = bh + (size_t)n0 * D_MODEL;
    bases[3] = bl + (size_t)n0 * D_MODEL;
    char* st = smem + s * STAGE_SM;
#pragma unroll
    for (int i = 0; i < 8; i++) {
        int idx = i * 256 + tid;      // 0..2047
        int t   = idx >> 9;           // tensor 0..3
        int rem = idx & 511;
        int r   = rem >> 2;           // row 0..127
        int sec = rem & 3;            // 16B sector 0..3
        const void* src = bases[t] + (size_t)r * D_MODEL + j * 32 + sec * 8;
        uint32_t dst = smem_to_u32(st + t * TILE_SM + r * ROW_B + sec * 16);
        CP_ASYNC16(dst, src);
    }
}

__global__ void __launch_bounds__(256, 1) gemm_mma(
    const __nv_bfloat16* __restrict__ a_h, const __nv_bfloat16* __restrict__ a_l,
    const __nv_bfloat16* __restrict__ b_h, const __nv_bfloat16* __restrict__ b_l,
    const float* __restrict__ bias, float* __restrict__ C, int scatter)
{
    extern __shared__ char smem[];
    const int tid  = threadIdx.x;
    const int wid  = tid >> 5;
    const int lane = tid & 31;
    const int wm   = wid >> 2;      // 0..1
    const int wn   = wid & 3;       // 0..3
    const int m0 = blockIdx.y * 128;
    const int n0 = blockIdx.x * 128;

    const int g  = lane >> 2;        // 0..7
    const int c2 = (lane & 3) * 4;   // byte offset of k-pair

    float acc[4][4][4];
#pragma unroll
    for (int i = 0; i < 4; i++)
#pragma unroll
        for (int j = 0; j < 4; j++)
#pragma unroll
            for (int k = 0; k < 4; k++) acc[i][j][k] = 0.f;

    load_stage(smem, 0, 0, tid, a_h, a_l, b_h, b_l, m0, n0);
    CP_COMMIT();
    load_stage(smem, 1, 1, tid, a_h, a_l, b_h, b_l, m0, n0);
    CP_COMMIT();

    for (int i = 0; i < NCHUNK; i++) {
        if (i + 2 < NCHUNK)
            load_stage(smem, (i + 2) % NSTAGE, i + 2, tid, a_h, a_l, b_h, b_l, m0, n0);
        CP_COMMIT();
        CP_WAIT2();          // chunk i's data resident
        __syncthreads();

        const char* base = smem + (i % NSTAGE) * STAGE_SM;
        const char* pAh = base;
        const char* pAl = base + TILE_SM;
        const char* pBh = base + 2 * TILE_SM;
        const char* pBl = base + 3 * TILE_SM;

#pragma unroll
        for (int ks = 0; ks < 2; ks++) {
            const int ko = ks * 32 + c2;

            uint32_t ah[4][4], al[4][4];
#pragma unroll
            for (int fm = 0; fm < 4; fm++) {
                const char* pa = pAh + (wm * 64 + fm * 16 + g) * ROW_B + ko;
                ah[fm][0] = *(const uint32_t*)(pa);
                ah[fm][1] = *(const uint32_t*)(pa + 8 * ROW_B);
                ah[fm][2] = *(const uint32_t*)(pa + 16);
                ah[fm][3] = *(const uint32_t*)(pa + 8 * ROW_B + 16);
                const char* pl = pAl + (wm * 64 + fm * 16 + g) * ROW_B + ko;
                al[fm][0] = *(const uint32_t*)(pl);
                al[fm][1] = *(const uint32_t*)(pl + 8 * ROW_B);
                al[fm][2] = *(const uint32_t*)(pl + 16);
                al[fm][3] = *(const uint32_t*)(pl + 8 * ROW_B + 16);
            }
            uint32_t bhf[4][2], blf[4][2];
#pragma unroll
            for (int fn = 0; fn < 4; fn++) {
                const char* pb = pBh + (wn * 32 + fn * 8 + g) * ROW_B + ko;
                bhf[fn][0] = *(const uint32_t*)(pb);
                bhf[fn][1] = *(const uint32_t*)(pb + 16);
                const char* pc = pBl + (wn * 32 + fn * 8 + g) * ROW_B + ko;
                blf[fn][0] = *(const uint32_t*)(pc);
                blf[fn][1] = *(const uint32_t*)(pc + 16);
            }
#pragma unroll
            for (int fm = 0; fm < 4; fm++)
#pragma unroll
                for (int fn = 0; fn < 4; fn++) {
                    MMA16816(acc[fm][fn], ah[fm], bhf[fn]);
                    MMA16816(acc[fm][fn], al[fm], bhf[fn]);
                    MMA16816(acc[fm][fn], ah[fm], blf[fn]);
                }
        }
        __syncthreads();
    }

    const int ccol = (lane & 3) * 2;
#pragma unroll
    for (int fn = 0; fn < 4; fn++) {
        int col = n0 + wn * 32 + fn * 8 + ccol;
        float b0 = bias[col], b1 = bias[col + 1];
#pragma unroll
        for (int fm = 0; fm < 4; fm++) {
            int mlo = m0 + wm * 64 + fm * 16 + g;
            int mhi = mlo + 8;
            float2 v0 = make_float2(acc[fm][fn][0] + b0, acc[fm][fn][1] + b1);
            float2 v1 = make_float2(acc[fm][fn][2] + b0, acc[fm][fn][3] + b1);
            if (!scatter) {
                *(float2*)&C[(size_t)mlo * D_MODEL + col] = v0;
                *(float2*)&C[(size_t)mhi * D_MODEL + col] = v1;
            } else {
                int h = col >> 6, d = col & 63;
                size_t i0 = (((size_t)((mlo >> 11) * N_HEADS + h) * SEQ) + (mlo & 2047)) * HEAD_DIM + d;
                size_t i1 = (((size_t)((mhi >> 11) * N_HEADS + h) * SEQ) + (mhi & 2047)) * HEAD_DIM + d;
                *(float2*)&C[i0] = v0;
                *(float2*)&C[i1] = v1;
            }
        }
    }
}

// ---------------------------------------------------------------------------
// Flash attention, fp32. 2 threads per q row (each owns 32 of 64 dims).
// ---------------------------------------------------------------------------
__global__ void __launch_bounds__(256) flash_attn_f32(
    const float* __restrict__ Q,
    const float* __restrict__ K,
    const float* __restrict__ V,
    float* __restrict__ O)
{
    const int tid = threadIdx.x;
    const int half = tid & 1;
    const int r = tid >> 1;
    const int bh = blockIdx.y;
    const int q0 = blockIdx.x * 128;
    const size_t base = (size_t)bh * SEQ * HEAD_DIM;

    __shared__ float4 sK[64 * 16];
    __shared__ float4 sV[64 * 16];

    float4 q[8];
    const float4* qp = (const float4*)&Q[base + (size_t)(q0 + r) * HEAD_DIM + half * 32];
#pragma unroll
    for (int d = 0; d < 8; d++) q[d] = qp[d];

    float4 o[8];
#pragma unroll
    for (int d = 0; d < 8; d++) o[d] = make_float4(0.f, 0.f, 0.f, 0.f);

    float mval = -1e30f;
    float l = 0.f;
    const float scale = 0.125f;

    for (int kt = 0; kt < SEQ; kt += 64) {
        const float4* kp = (const float4*)&K[base + (size_t)kt * HEAD_DIM];
        const float4* vp = (const float4*)&V[base + (size_t)kt * HEAD_DIM];
#pragma unroll
        for (int p = 0; p < 4; p++) {
            sK[tid + p * 256] = kp[tid + p * 256];
            sV[tid + p * 256] = vp[tid + p * 256];
        }
        __syncthreads();

#pragma unroll 2
        for (int j = 0; j < 64; j++) {
            const float4* kj = &sK[j * 16 + half * 8];
            float s0 = 0.f, s1 = 0.f, s2 = 0.f, s3 = 0.f;
#pragma unroll
            for (int d = 0; d < 8; d++) {
                float4 kk = kj[d];
                s0 += q[d].x * kk.x;
                s1 += q[d].y * kk.y;
                s2 += q[d].z * kk.z;
                s3 += q[d].w * kk.w;
            }
            float sh = (s0 + s1) + (s2 + s3);
            sh += __shfl_xor_sync(0xffffffffu, sh, 1);
            float s = sh * scale;

            const float4* vj = &sV[j * 16 + half * 8];
            if (s <= mval) {
                float p = __expf(s - mval);
                l += p;
#pragma unroll
                for (int d = 0; d < 8; d++) {
                    float4 vv = vj[d];
                    o[d].x += p * vv.x; o[d].y += p * vv.y;
                    o[d].z += p * vv.z; o[d].w += p * vv.w;
                }
            } else {
                float corr = __expf(mval - s);
                mval = s;
                l = l * corr + 1.f;
#pragma unroll
                for (int d = 0; d < 8; d++) {
                    float4 vv = vj[d];
                    o[d].x = o[d].x * corr + vv.x;
                    o[d].y = o[d].y * corr + vv.y;
                    o[d].z = o[d].z * corr + vv.z;
                    o[d].w = o[d].w * corr + vv.w;
                }
            }
        }
        __syncthreads();
    }

    const float inv = 1.f / l;
    const int b = bh >> 4;
    const int h = bh & 15;
    float4* op = (float4*)&O[((size_t)b * SEQ + (q0 + r)) * D_MODEL + h * HEAD_DIM + half * 32];
#pragma unroll
    for (int d = 0; d < 8; d++) {
        float4 v = o[d];
        v.x *= inv; v.y *= inv; v.z *= inv; v.w *= inv;
        op[d] = v;
    }
}

// ---------------------------------------------------------------------------
extern "C" void kernel_launch(void* const* d_in, const int* in_sizes, int n_in,
                              void* d_out, int out_size)
{
    const float* query = (const float*)d_in[0];
    const float* key   = (const float*)d_in[1];
    const float* value = (const float*)d_in[2];
    const float* bq    = (const float*)d_in[4];
    const float* bk    = (const float*)d_in[6];
    const float* bv    = (const float*)d_in[8];
    const float* bo    = (const float*)d_in[10];
    float* out = (float*)d_out;

    float *qp, *kp, *vp, *op;
    cudaGetSymbolAddress((void**)&qp, g_Q);
    cudaGetSymbolAddress((void**)&kp, g_K);
    cudaGetSymbolAddress((void**)&vp, g_V);
    cudaGetSymbolAddress((void**)&op, g_O);

    __nv_bfloat16 *qh, *ql, *kh, *kl, *vh, *vl, *oh, *ol;
    __nv_bfloat16 *wqh, *wql, *wkh, *wkl, *wvh, *wvl, *woh, *wol;
    cudaGetSymbolAddress((void**)&qh, s_qh);   cudaGetSymbolAddress((void**)&ql, s_ql);
    cudaGetSymbolAddress((void**)&kh, s_kh);   cudaGetSymbolAddress((void**)&kl, s_kl);
    cudaGetSymbolAddress((void**)&vh, s_vh);   cudaGetSymbolAddress((void**)&vl, s_vl);
    cudaGetSymbolAddress((void**)&oh, s_oh);   cudaGetSymbolAddress((void**)&ol, s_ol);
    cudaGetSymbolAddress((void**)&wqh, s_wqh); cudaGetSymbolAddress((void**)&wql, s_wql);
    cudaGetSymbolAddress((void**)&wkh, s_wkh); cudaGetSymbolAddress((void**)&wkl, s_wkl);
    cudaGetSymbolAddress((void**)&wvh, s_wvh); cudaGetSymbolAddress((void**)&wvl, s_wvl);
    cudaGetSymbolAddress((void**)&woh, s_woh); cudaGetSymbolAddress((void**)&wol, s_wol);

    cudaFuncSetAttribute(gemm_mma, cudaFuncAttributeMaxDynamicSharedMemorySize, GEMM_SMEM);

    const int n4_act = M_TOTAL * D_MODEL / 4;
    const int n4_w   = D_MODEL * D_MODEL / 4;
    const int gb_act = (n4_act + 255) / 256;
    const int gb_w   = (n4_w + 255) / 256;

    cvt_split<<<gb_act, 256>>>((const float4*)query, (__nv_bfloat162*)qh, (__nv_bfloat162*)ql, n4_act);
    cvt_split<<<gb_act, 256>>>((const float4*)key,   (__nv_bfloat162*)kh, (__nv_bfloat162*)kl, n4_act);
    cvt_split<<<gb_act, 256>>>((const float4*)value, (__nv_bfloat162*)vh, (__nv_bfloat162*)vl, n4_act);
    cvt_split<<<gb_w, 256>>>((const float4*)d_in[3], (__nv_bfloat162*)wqh, (__nv_bfloat162*)wql, n4_w);
    cvt_split<<<gb_w, 256>>>((const float4*)d_in[5], (__nv_bfloat162*)wkh, (__nv_bfloat162*)wkl, n4_w);
    cvt_split<<<gb_w, 256>>>((const float4*)d_in[7], (__nv_bfloat162*)wvh, (__nv_bfloat162*)wvl, n4_w);
    cvt_split<<<gb_w, 256>>>((const float4*)d_in[9], (__nv_bfloat162*)woh, (__nv_bfloat162*)wol, n4_w);

    dim3 gemm_grid(D_MODEL / 128, M_TOTAL / 128);  // (8, 64)

    gemm_mma<<<gemm_grid, 256, GEMM_SMEM>>>(qh, ql, wqh, wql, bq, qp, 1);
    gemm_mma<<<gemm_grid, 256, GEMM_SMEM>>>(kh, kl, wkh, wkl, bk, kp, 1);
    gemm_mma<<<gemm_grid, 256, GEMM_SMEM>>>(vh, vl, wvh, wvl, bv, vp, 1);

    dim3 attn_grid(SEQ / 128, BATCH * N_HEADS);  // (16, 64)
    flash_attn_f32<<<attn_grid, 256>>>(qp, kp, vp, op);

    cvt_split<<<gb_act, 256>>>((const float4*)op, (__nv_bfloat162*)oh, (__nv_bfloat162*)ol, n4_act);
    gemm_mma<<<gemm_grid, 256, GEMM_SMEM>>>(oh, ol, woh, wol, bo, out, 0);
}

// round 4
// speedup vs baseline: 3.4198x; 3.4198x over previous
#include <cuda_runtime.h>
#include <cuda_bf16.h>
#include <cstdint>

#define D_MODEL 1024
#define N_HEADS 16
#define HEAD_DIM 64
#define BATCH 4
#define SEQ 2048
#define M_TOTAL (BATCH * SEQ)  // 8192

// ---------------------------------------------------------------------------
// Scratch (__device__ globals; no allocation allowed)
// ---------------------------------------------------------------------------
// activation input split (reused sequentially for query/key/value)
__device__ __nv_bfloat16 g_xh[(size_t)M_TOTAL * D_MODEL];
__device__ __nv_bfloat16 g_xl[(size_t)M_TOTAL * D_MODEL];
// projected Q/K/V, bf16 hi/lo, [B,H,S,D] layout (Q pre-scaled by 0.125)
__device__ __nv_bfloat16 g_qh[(size_t)M_TOTAL * D_MODEL];
__device__ __nv_bfloat16 g_ql[(size_t)M_TOTAL * D_MODEL];
__device__ __nv_bfloat16 g_kh[(size_t)M_TOTAL * D_MODEL];
__device__ __nv_bfloat16 g_kl[(size_t)M_TOTAL * D_MODEL];
__device__ __nv_bfloat16 g_vh[(size_t)M_TOTAL * D_MODEL];
__device__ __nv_bfloat16 g_vl[(size_t)M_TOTAL * D_MODEL];
// attention output split, [B,S,D_MODEL]
__device__ __nv_bfloat16 g_oh[(size_t)M_TOTAL * D_MODEL];
__device__ __nv_bfloat16 g_ol[(size_t)M_TOTAL * D_MODEL];
// weight splits
__device__ __nv_bfloat16 s_wqh[(size_t)D_MODEL * D_MODEL];
__device__ __nv_bfloat16 s_wql[(size_t)D_MODEL * D_MODEL];
__device__ __nv_bfloat16 s_wkh[(size_t)D_MODEL * D_MODEL];
__device__ __nv_bfloat16 s_wkl[(size_t)D_MODEL * D_MODEL];
__device__ __nv_bfloat16 s_wvh[(size_t)D_MODEL * D_MODEL];
__device__ __nv_bfloat16 s_wvl[(size_t)D_MODEL * D_MODEL];
__device__ __nv_bfloat16 s_woh[(size_t)D_MODEL * D_MODEL];
__device__ __nv_bfloat16 s_wol[(size_t)D_MODEL * D_MODEL];

// ---------------------------------------------------------------------------
// PTX helpers (baseline ISA: sm_80-level features only)
// ---------------------------------------------------------------------------
__device__ __forceinline__ uint32_t smem_to_u32(const void* p) {
    uint32_t a;
    asm("{ .reg .u64 t; cvta.to.shared.u64 t, %1; cvt.u32.u64 %0, t; }" : "=r"(a) : "l"(p));
    return a;
}

#define CP_ASYNC16(dst, src) \
    asm volatile("cp.async.cg.shared.global [%0], [%1], 16;\n" :: "r"(dst), "l"(src))
#define CP_COMMIT() asm volatile("cp.async.commit_group;" ::: "memory")
#define CP_WAIT0()  asm volatile("cp.async.wait_group 0;" ::: "memory")
#define CP_WAIT1()  asm volatile("cp.async.wait_group 1;" ::: "memory")

#define LDSM4(r, a) \
    asm volatile("ldmatrix.sync.aligned.m8n8.x4.shared.b16 {%0,%1,%2,%3}, [%4];" \
        : "=r"((r)[0]), "=r"((r)[1]), "=r"((r)[2]), "=r"((r)[3]) : "r"(a))
#define LDSM4T(r, a) \
    asm volatile("ldmatrix.sync.aligned.m8n8.x4.trans.shared.b16 {%0,%1,%2,%3}, [%4];" \
        : "=r"((r)[0]), "=r"((r)[1]), "=r"((r)[2]), "=r"((r)[3]) : "r"(a))

// d += a * b  (m16n8k16, bf16 in, f32 accum)
#define MMA(d, a, b0v, b1v) \
    asm volatile("mma.sync.aligned.m16n8k16.row.col.f32.bf16.bf16.f32 " \
        "{%0,%1,%2,%3}, {%4,%5,%6,%7}, {%8,%9}, {%0,%1,%2,%3};" \
        : "+f"((d)[0]), "+f"((d)[1]), "+f"((d)[2]), "+f"((d)[3]) \
        : "r"((a)[0]), "r"((a)[1]), "r"((a)[2]), "r"((a)[3]), \
          "r"(b0v), "r"(b1v))

__device__ __forceinline__ uint32_t pack_bf16x2(float lo, float hi) {
    __nv_bfloat162 h = __floats2bfloat162_rn(lo, hi);   // .x = lo half
    return reinterpret_cast<uint32_t&>(h);
}

// ---------------------------------------------------------------------------
// fp32 -> (bf16 hi, bf16 lo) split
// ---------------------------------------------------------------------------
__global__ void __launch_bounds__(256) cvt_split(
    const float4* __restrict__ x,
    __nv_bfloat162* __restrict__ hi,
    __nv_bfloat162* __restrict__ lo,
    int n4)
{
    int i = blockIdx.x * 256 + threadIdx.x;
    if (i >= n4) return;
    float4 v = x[i];
    __nv_bfloat16 h0 = __float2bfloat16(v.x);
    __nv_bfloat16 h1 = __float2bfloat16(v.y);
    __nv_bfloat16 h2 = __float2bfloat16(v.z);
    __nv_bfloat16 h3 = __float2bfloat16(v.w);
    __nv_bfloat16 l0 = __float2bfloat16(v.x - __bfloat162float(h0));
    __nv_bfloat16 l1 = __float2bfloat16(v.y - __bfloat162float(h1));
    __nv_bfloat16 l2 = __float2bfloat16(v.z - __bfloat162float(h2));
    __nv_bfloat16 l3 = __float2bfloat16(v.w - __bfloat162float(h3));
    hi[i * 2 + 0] = __halves2bfloat162(h0, h1);
    hi[i * 2 + 1] = __halves2bfloat162(h2, h3);
    lo[i * 2 + 0] = __halves2bfloat162(l0, l1);
    lo[i * 2 + 1] = __halves2bfloat162(l2, l3);
}

// ---------------------------------------------------------------------------
// Split-bf16 GEMM via mma.sync + ldmatrix.
// C[8192,1024] = A*B^T + bias;  D = Ah*Bh + Al*Bh + Ah*Bl.
// CTA 128x128, 8 warps (warp tile 64x32), K-chunk 32, 3-stage cp.async.
// mode 0: C = fp32 [m][1024]; mode 1: scatter (val*scale) as bf16 hi/lo into
//         [B,H,S,D] tensors Ch/Cl.
// ---------------------------------------------------------------------------
#define ROW_B 80
#define TILE_SM (128 * ROW_B)          // 10240
#define STAGE_SM (4 * TILE_SM)         // 40960
#define NSTAGE 3
#define GEMM_SMEM (NSTAGE * STAGE_SM)  // 122880
#define NCHUNK 32

__device__ __forceinline__ void g_load_stage(
    uint32_t smem_u, int s, int j, int tid,
    const __nv_bfloat16* ah, const __nv_bfloat16* al,
    const __nv_bfloat16* bh, const __nv_bfloat16* bl,
    int m0, int n0)
{
    const __nv_bfloat16* bases[4];
    bases[0] = ah + (size_t)m0 * D_MODEL;
    bases[1] = al + (size_t)m0 * D_MODEL;
    bases[2] = bh + (size_t)n0 * D_MODEL;
    bases[3] = bl + (size_t)n0 * D_MODEL;
    uint32_t st = smem_u + s * STAGE_SM;
#pragma unroll
    for (int i = 0; i < 8; i++) {
        int idx = i * 256 + tid;      // 0..2047
        int t   = idx >> 9;
        int rem = idx & 511;
        int r   = rem >> 2;           // row 0..127
        int sec = rem & 3;            // 16B sector
        const void* src = bases[t] + (size_t)r * D_MODEL + j * 32 + sec * 8;
        CP_ASYNC16(st + t * TILE_SM + r * ROW_B + sec * 16, src);
    }
}

__global__ void __launch_bounds__(256, 1) gemm_mma(
    const __nv_bfloat16* __restrict__ a_h, const __nv_bfloat16* __restrict__ a_l,
    const __nv_bfloat16* __restrict__ b_h, const __nv_bfloat16* __restrict__ b_l,
    const float* __restrict__ bias,
    float* __restrict__ Cf,
    __nv_bfloat16* __restrict__ Ch, __nv_bfloat16* __restrict__ Cl,
    float scale, int mode)
{
    extern __shared__ char smem[];
    const uint32_t smem_u = smem_to_u32(smem);
    const int tid  = threadIdx.x;
    const int wid  = tid >> 5;
    const int lane = tid & 31;
    const int wm   = wid >> 2;
    const int wn   = wid & 3;
    const int m0 = blockIdx.y * 128;
    const int n0 = blockIdx.x * 128;

    const int ldrow = (lane & 7) + ((lane >> 3) & 1) * 8;  // ldmatrix row-in-16
    const int ldcol = (lane >> 4) * 16;                    // 0 or 16

    float acc[4][4][4];
#pragma unroll
    for (int i = 0; i < 4; i++)
#pragma unroll
        for (int j = 0; j < 4; j++)
#pragma unroll
            for (int k = 0; k < 4; k++) acc[i][j][k] = 0.f;

    g_load_stage(smem_u, 0, 0, tid, a_h, a_l, b_h, b_l, m0, n0);
    CP_COMMIT();
    g_load_stage(smem_u, 1, 1, tid, a_h, a_l, b_h, b_l, m0, n0);
    CP_COMMIT();

    for (int i = 0; i < NCHUNK; i++) {
        // top of iter: pending groups = {i, i+1} (i<=30) or {31}
        if (i == NCHUNK - 1) { CP_WAIT0(); } else { CP_WAIT1(); }
        __syncthreads();   // all warps done reading stage i-1; stage i visible
        if (i + 2 < NCHUNK) {
            g_load_stage(smem_u, (i + 2) % NSTAGE, i + 2, tid, a_h, a_l, b_h, b_l, m0, n0);
            CP_COMMIT();
        }

        const uint32_t base = smem_u + (i % NSTAGE) * STAGE_SM;
        const uint32_t pAh = base;
        const uint32_t pAl = base + TILE_SM;
        const uint32_t pBh = base + 2 * TILE_SM;
        const uint32_t pBl = base + 3 * TILE_SM;

#pragma unroll
        for (int ks = 0; ks < 2; ks++) {
            const int kb = ks * 32 + ldcol;
            uint32_t afh[4][4], afl[4][4];
#pragma unroll
            for (int fm = 0; fm < 4; fm++) {
                uint32_t ra = (wm * 64 + fm * 16 + ldrow) * ROW_B + kb;
                LDSM4(afh[fm], pAh + ra);
                LDSM4(afl[fm], pAl + ra);
            }
            uint32_t bfh[2][4], bfl[2][4];
#pragma unroll
            for (int fp = 0; fp < 2; fp++) {
                uint32_t rb = (wn * 32 + fp * 16 + ldrow) * ROW_B + kb;
                LDSM4(bfh[fp], pBh + rb);
                LDSM4(bfl[fp], pBl + rb);
            }
#pragma unroll
            for (int fm = 0; fm < 4; fm++)
#pragma unroll
                for (int fn = 0; fn < 4; fn++) {
                    const int fp = fn >> 1, sl = fn & 1;
                    // non-trans ldsm: fn_even b={r0,r2}, fn_odd b={r1,r3}
                    MMA(acc[fm][fn], afh[fm], bfh[fp][sl], bfh[fp][sl + 2]);
                    MMA(acc[fm][fn], afl[fm], bfh[fp][sl], bfh[fp][sl + 2]);
                    MMA(acc[fm][fn], afh[fm], bfl[fp][sl], bfl[fp][sl + 2]);
                }
        }
        __syncthreads();  // warps done with stage i before next iter's loads
    }

    const int g = lane >> 2;
    const int ccol = (lane & 3) * 2;
#pragma unroll
    for (int fn = 0; fn < 4; fn++) {
        int col = n0 + wn * 32 + fn * 8 + ccol;
        float b0 = bias[col], b1 = bias[col + 1];
#pragma unroll
        for (int fm = 0; fm < 4; fm++) {
            int mlo = m0 + wm * 64 + fm * 16 + g;
            int mhi = mlo + 8;
            float v0 = acc[fm][fn][0] + b0, v1 = acc[fm][fn][1] + b1;
            float v2 = acc[fm][fn][2] + b0, v3 = acc[fm][fn][3] + b1;
            if (mode == 0) {
                *(float2*)&Cf[(size_t)mlo * D_MODEL + col] = make_float2(v0, v1);
                *(float2*)&Cf[(size_t)mhi * D_MODEL + col] = make_float2(v2, v3);
            } else {
                v0 *= scale; v1 *= scale; v2 *= scale; v3 *= scale;
                int h = col >> 6, d = col & 63;
                size_t i0 = (((size_t)((mlo >> 11) * N_HEADS + h) * SEQ) + (mlo & 2047)) * HEAD_DIM + d;
                size_t i1 = (((size_t)((mhi >> 11) * N_HEADS + h) * SEQ) + (mhi & 2047)) * HEAD_DIM + d;
                __nv_bfloat162 h01 = __floats2bfloat162_rn(v0, v1);
                __nv_bfloat162 h23 = __floats2bfloat162_rn(v2, v3);
                __nv_bfloat162 l01 = __floats2bfloat162_rn(
                    v0 - __bfloat162float(h01.x), v1 - __bfloat162float(h01.y));
                __nv_bfloat162 l23 = __floats2bfloat162_rn(
                    v2 - __bfloat162float(h23.x), v3 - __bfloat162float(h23.y));
                *(__nv_bfloat162*)&Ch[i0] = h01;
                *(__nv_bfloat162*)&Ch[i1] = h23;
                *(__nv_bfloat162*)&Cl[i0] = l01;
                *(__nv_bfloat162*)&Cl[i1] = l23;
            }
        }
    }
}

// ---------------------------------------------------------------------------
// Flash attention on mma.sync, split-bf16 on QK^T and P*V.
// CTA = 128 q rows x one (b,h); 8 warps, warp = 16 q rows x full 64-key tile.
// Q pre-scaled by 0.125. Double-buffered K/V tiles via cp.async.
// grid = (16, 64), 256 threads.
// ---------------------------------------------------------------------------
#define AROW 144                     // 128B data + 16B pad
#define AQ_T (128 * AROW)            // 18432 per Q tensor
#define AK_T (64 * AROW)             // 9216 per KV tensor
#define AKV_BUF (4 * AK_T)           // 36864 (kh,kl,vh,vl)
#define ATT_SMEM (2 * AQ_T + 2 * AKV_BUF)  // 110592

__device__ __forceinline__ void a_load_kv(
    uint32_t kvsu, int buf, int tile, int tid, size_t gbase,
    const __nv_bfloat16* kh, const __nv_bfloat16* kl,
    const __nv_bfloat16* vh, const __nv_bfloat16* vl)
{
    const __nv_bfloat16* srcs[4] = {
        kh + gbase + (size_t)tile * 64 * HEAD_DIM,
        kl + gbase + (size_t)tile * 64 * HEAD_DIM,
        vh + gbase + (size_t)tile * 64 * HEAD_DIM,
        vl + gbase + (size_t)tile * 64 * HEAD_DIM };
    uint32_t dstb = kvsu + buf * AKV_BUF;
#pragma unroll
    for (int it = 0; it < 8; it++) {
        int idx = it * 256 + tid;   // 0..2047
        int t   = idx >> 9;
        int rem = idx & 511;
        int row = rem >> 3;
        int sec = rem & 7;
        CP_ASYNC16(dstb + t * AK_T + row * AROW + sec * 16,
                   srcs[t] + (size_t)row * HEAD_DIM + sec * 8);
    }
}

__global__ void __launch_bounds__(256, 1) attn_mma(
    const __nv_bfloat16* __restrict__ qh, const __nv_bfloat16* __restrict__ ql,
    const __nv_bfloat16* __restrict__ kh, const __nv_bfloat16* __restrict__ kl,
    const __nv_bfloat16* __restrict__ vh, const __nv_bfloat16* __restrict__ vl,
    __nv_bfloat16* __restrict__ oh, __nv_bfloat16* __restrict__ ol)
{
    extern __shared__ char smem[];
    const uint32_t su = smem_to_u32(smem);
    const int tid  = threadIdx.x;
    const int wid  = tid >> 5;
    const int lane = tid & 31;
    const int g    = lane >> 2;
    const int bh   = blockIdx.y;
    const int q0   = blockIdx.x * 128;
    const size_t gbase = (size_t)bh * SEQ * HEAD_DIM;

    const int ldrow = (lane & 7) + ((lane >> 3) & 1) * 8;
    const int ldcol = (lane >> 4) * 16;

    // issue Q tile loads (2 tensors x 128 rows x 128B)
    {
        const __nv_bfloat16* qs[2] = { qh + gbase + (size_t)q0 * HEAD_DIM,
                                       ql + gbase + (size_t)q0 * HEAD_DIM };
#pragma unroll
        for (int it = 0; it < 8; it++) {
            int idx = it * 256 + tid;   // 0..2047
            int t   = idx >> 10;
            int rem = idx & 1023;
            int row = rem >> 3;
            int sec = rem & 7;
            CP_ASYNC16(su + t * AQ_T + row * AROW + sec * 16,
                       qs[t] + (size_t)row * HEAD_DIM + sec * 8);
        }
    }
    CP_COMMIT();
    const uint32_t kvsu = su + 2 * AQ_T;
    a_load_kv(kvsu, 0, 0, tid, gbase, kh, kl, vh, vl);
    CP_COMMIT();

    CP_WAIT1();        // Q tile arrived (KV0 may still fly)
    __syncthreads();

    // Q fragments (persistent)
    uint32_t qfh[4][4], qfl[4][4];
    {
        uint32_t qb = su + (wid * 16 + ldrow) * AROW + ldcol;
#pragma unroll
        for (int ks = 0; ks < 4; ks++) {
            LDSM4(qfh[ks], qb + ks * 32);
            LDSM4(qfl[ks], qb + AQ_T + ks * 32);
        }
    }

    float O[8][4];
#pragma unroll
    for (int f = 0; f < 8; f++)
#pragma unroll
        for (int k = 0; k < 4; k++) O[f][k] = 0.f;
    float rm0 = -1e30f, rm1 = -1e30f;
    float rl0 = 0.f, rl1 = 0.f;

    for (int t = 0; t < SEQ / 64; t++) {
        CP_WAIT0();          // KV tile t resident
        __syncthreads();     // visible to all warps; prior reads of buf (t+1)&1 done
        if (t + 1 < SEQ / 64) {
            a_load_kv(kvsu, (t + 1) & 1, t + 1, tid, gbase, kh, kl, vh, vl);
            CP_COMMIT();
        }
        const uint32_t kb_h = kvsu + (t & 1) * AKV_BUF;
        const uint32_t kb_l = kb_h + AK_T;
        const uint32_t vb_h = kb_h + 2 * AK_T;
        const uint32_t vb_l = kb_h + 3 * AK_T;

        // ---- S = Qs*K^T (3-pass split), m16 x n64 per warp ----
        float S[8][4];
#pragma unroll
        for (int f = 0; f < 8; f++)
#pragma unroll
            for (int k = 0; k < 4; k++) S[f][k] = 0.f;

#pragma unroll
        for (int ks = 0; ks < 4; ks++) {
            const int kc = ks * 32 + ldcol;
            uint32_t kfh[4][4], kfl[4][4];
#pragma unroll
            for (int p = 0; p < 4; p++) {
                uint32_t ra = (p * 16 + ldrow) * AROW + kc;
                LDSM4(kfh[p], kb_h + ra);
                LDSM4(kfl[p], kb_l + ra);
            }
#pragma unroll
            for (int fn = 0; fn < 8; fn++) {
                const int p = fn >> 1, sl = fn & 1;
                MMA(S[fn], qfh[ks], kfh[p][sl], kfh[p][sl + 2]);
                MMA(S[fn], qfl[ks], kfh[p][sl], kfh[p][sl + 2]);
                MMA(S[fn], qfh[ks], kfl[p][sl], kfl[p][sl + 2]);
            }
        }

        // ---- online softmax (rows g and g+8; quad lanes share a row) ----
        float mx0 = -1e30f, mx1 = -1e30f;
#pragma unroll
        for (int f = 0; f < 8; f++) {
            mx0 = fmaxf(mx0, fmaxf(S[f][0], S[f][1]));
            mx1 = fmaxf(mx1, fmaxf(S[f][2], S[f][3]));
        }
        mx0 = fmaxf(mx0, __shfl_xor_sync(0xffffffffu, mx0, 1));
        mx0 = fmaxf(mx0, __shfl_xor_sync(0xffffffffu, mx0, 2));
        mx1 = fmaxf(mx1, __shfl_xor_sync(0xffffffffu, mx1, 1));
        mx1 = fmaxf(mx1, __shfl_xor_sync(0xffffffffu, mx1, 2));
        float mn0 = fmaxf(rm0, mx0), mn1 = fmaxf(rm1, mx1);
        float c0 = __expf(rm0 - mn0), c1 = __expf(rm1 - mn1);
        rm0 = mn0; rm1 = mn1;

        float s0 = 0.f, s1 = 0.f;
#pragma unroll
        for (int f = 0; f < 8; f++) {
            S[f][0] = __expf(S[f][0] - mn0); s0 += S[f][0];
            S[f][1] = __expf(S[f][1] - mn0); s0 += S[f][1];
            S[f][2] = __expf(S[f][2] - mn1); s1 += S[f][2];
            S[f][3] = __expf(S[f][3] - mn1); s1 += S[f][3];
        }
        s0 += __shfl_xor_sync(0xffffffffu, s0, 1);
        s0 += __shfl_xor_sync(0xffffffffu, s0, 2);
        s1 += __shfl_xor_sync(0xffffffffu, s1, 1);
        s1 += __shfl_xor_sync(0xffffffffu, s1, 2);
        rl0 = rl0 * c0 + s0;
        rl1 = rl1 * c1 + s1;
#pragma unroll
        for (int f = 0; f < 8; f++) {
            O[f][0] *= c0; O[f][1] *= c0;
            O[f][2] *= c1; O[f][3] *= c1;
        }

        // ---- P -> split bf16 A-fragments (k = key dim) ----
        uint32_t pah[4][4], pal[4][4];
#pragma unroll
        for (int kj = 0; kj < 4; kj++) {
            const int f0 = 2 * kj, f1 = f0 + 1;
            float x0 = S[f0][0], x1 = S[f0][1], x2 = S[f0][2], x3 = S[f0][3];
            float y0 = S[f1][0], y1 = S[f1][1], y2 = S[f1][2], y3 = S[f1][3];
            __nv_bfloat162 h;
            h = __floats2bfloat162_rn(x0, x1); pah[kj][0] = reinterpret_cast<uint32_t&>(h);
            pal[kj][0] = pack_bf16x2(x0 - __bfloat162float(h.x), x1 - __bfloat162float(h.y));
            h = __floats2bfloat162_rn(x2, x3); pah[kj][1] = reinterpret_cast<uint32_t&>(h);
            pal[kj][1] = pack_bf16x2(x2 - __bfloat162float(h.x), x3 - __bfloat162float(h.y));
            h = __floats2bfloat162_rn(y0, y1); pah[kj][2] = reinterpret_cast<uint32_t&>(h);
            pal[kj][2] = pack_bf16x2(y0 - __bfloat162float(h.x), y1 - __bfloat162float(h.y));
            h = __floats2bfloat162_rn(y2, y3); pah[kj][3] = reinterpret_cast<uint32_t&>(h);
            pal[kj][3] = pack_bf16x2(y2 - __bfloat162float(h.x), y3 - __bfloat162float(h.y));
        }

        // ---- O += P*V (3-pass split); V^T fragments via ldmatrix.trans ----
#pragma unroll
        for (int kj = 0; kj < 4; kj++) {
            uint32_t vfh[4][4], vfl[4][4];
#pragma unroll
            for (int p = 0; p < 4; p++) {
                uint32_t ra = (kj * 16 + ldrow) * AROW + p * 32 + ldcol;
                LDSM4T(vfh[p], vb_h + ra);
                LDSM4T(vfl[p], vb_l + ra);
            }
#pragma unroll
            for (int fn = 0; fn < 8; fn++) {
                const int p = fn >> 1, sl = (fn & 1) * 2;
                // trans ldsm: fn_even b={r0,r1}, fn_odd b={r2,r3}
                MMA(O[fn], pah[kj], vfh[p][sl], vfh[p][sl + 1]);
                MMA(O[fn], pal[kj], vfh[p][sl], vfh[p][sl + 1]);
                MMA(O[fn], pah[kj], vfl[p][sl], vfl[p][sl + 1]);
            }
        }
    }

    // ---- epilogue: x = O / l, write bf16 hi/lo to [B,S,1024] ----
    const float inv0 = 1.f / rl0;
    const float inv1 = 1.f / rl1;
    const int b = bh >> 4;
    const int h = bh & 15;
    const int r0g = q0 + wid * 16 + g;
    const int r1g = r0g + 8;
#pragma unroll
    for (int fn = 0; fn < 8; fn++) {
        int col = h * HEAD_DIM + fn * 8 + (lane & 3) * 2;
        size_t i0 = ((size_t)(b * SEQ + r0g)) * D_MODEL + col;
        size_t i1 = ((size_t)(b * SEQ + r1g)) * D_MODEL + col;
        float v0 = O[fn][0] * inv0, v1 = O[fn][1] * inv0;
        float v2 = O[fn][2] * inv1, v3 = O[fn][3] * inv1;
        __nv_bfloat162 h01 = __floats2bfloat162_rn(v0, v1);
        __nv_bfloat162 h23 = __floats2bfloat162_rn(v2, v3);
        __nv_bfloat162 l01 = __floats2bfloat162_rn(
            v0 - __bfloat162float(h01.x), v1 - __bfloat162float(h01.y));
        __nv_bfloat162 l23 = __floats2bfloat162_rn(
            v2 - __bfloat162float(h23.x), v3 - __bfloat162float(h23.y));
        *(__nv_bfloat162*)&oh[i0] = h01;
        *(__nv_bfloat162*)&oh[i1] = h23;
        *(__nv_bfloat162*)&ol[i0] = l01;
        *(__nv_bfloat162*)&ol[i1] = l23;
    }
}

// ---------------------------------------------------------------------------
extern "C" void kernel_launch(void* const* d_in, const int* in_sizes, int n_in,
                              void* d_out, int out_size)
{
    const float* query = (const float*)d_in[0];
    const float* key   = (const float*)d_in[1];
    const float* value = (const float*)d_in[2];
    const float* bq    = (const float*)d_in[4];
    const float* bk    = (const float*)d_in[6];
    const float* bv    = (const float*)d_in[8];
    const float* bo    = (const float*)d_in[10];
    float* out = (float*)d_out;

    __nv_bfloat16 *xh, *xl, *qh, *ql, *kh, *kl, *vh, *vl, *oh, *ol;
    __nv_bfloat16 *wqh, *wql, *wkh, *wkl, *wvh, *wvl, *woh, *wol;
    cudaGetSymbolAddress((void**)&xh, g_xh);   cudaGetSymbolAddress((void**)&xl, g_xl);
    cudaGetSymbolAddress((void**)&qh, g_qh);   cudaGetSymbolAddress((void**)&ql, g_ql);
    cudaGetSymbolAddress((void**)&kh, g_kh);   cudaGetSymbolAddress((void**)&kl, g_kl);
    cudaGetSymbolAddress((void**)&vh, g_vh);   cudaGetSymbolAddress((void**)&vl, g_vl);
    cudaGetSymbolAddress((void**)&oh, g_oh);   cudaGetSymbolAddress((void**)&ol, g_ol);
    cudaGetSymbolAddress((void**)&wqh, s_wqh); cudaGetSymbolAddress((void**)&wql, s_wql);
    cudaGetSymbolAddress((void**)&wkh, s_wkh); cudaGetSymbolAddress((void**)&wkl, s_wkl);
    cudaGetSymbolAddress((void**)&wvh, s_wvh); cudaGetSymbolAddress((void**)&wvl, s_wvl);
    cudaGetSymbolAddress((void**)&woh, s_woh); cudaGetSymbolAddress((void**)&wol, s_wol);

    cudaFuncSetAttribute(gemm_mma, cudaFuncAttributeMaxDynamicSharedMemorySize, GEMM_SMEM);
    cudaFuncSetAttribute(attn_mma, cudaFuncAttributeMaxDynamicSharedMemorySize, ATT_SMEM);

    const int n4_act = M_TOTAL * D_MODEL / 4;
    const int n4_w   = D_MODEL * D_MODEL / 4;
    const int gb_act = (n4_act + 255) / 256;
    const int gb_w   = (n4_w + 255) / 256;

    // weight splits
    cvt_split<<<gb_w, 256>>>((const float4*)d_in[3], (__nv_bfloat162*)wqh, (__nv_bfloat162*)wql, n4_w);
    cvt_split<<<gb_w, 256>>>((const float4*)d_in[5], (__nv_bfloat162*)wkh, (__nv_bfloat162*)wkl, n4_w);
    cvt_split<<<gb_w, 256>>>((const float4*)d_in[7], (__nv_bfloat162*)wvh, (__nv_bfloat162*)wvl, n4_w);
    cvt_split<<<gb_w, 256>>>((const float4*)d_in[9], (__nv_bfloat162*)woh, (__nv_bfloat162*)wol, n4_w);

    dim3 gemm_grid(D_MODEL / 128, M_TOTAL / 128);  // (8, 64)

    // Q projection (scaled by 1/sqrt(HEAD_DIM))
    cvt_split<<<gb_act, 256>>>((const float4*)query, (__nv_bfloat162*)xh, (__nv_bfloat162*)xl, n4_act);
    gemm_mma<<<gemm_grid, 256, GEMM_SMEM>>>(xh, xl, wqh, wql, bq, nullptr, qh, ql, 0.125f, 1);
    // K projection
    cvt_split<<<gb_act, 256>>>((const float4*)key, (__nv_bfloat162*)xh, (__nv_bfloat162*)xl, n4_act);
    gemm_mma<<<gemm_grid, 256, GEMM_SMEM>>>(xh, xl, wkh, wkl, bk, nullptr, kh, kl, 1.0f, 1);
    // V projection
    cvt_split<<<gb_act, 256>>>((const float4*)value, (__nv_bfloat162*)xh, (__nv_bfloat162*)xl, n4_act);
    gemm_mma<<<gemm_grid, 256, GEMM_SMEM>>>(xh, xl, wvh, wvl, bv, nullptr, vh, vl, 1.0f, 1);

    // attention
    dim3 attn_grid(SEQ / 128, BATCH * N_HEADS);  // (16, 64)
    attn_mma<<<attn_grid, 256, ATT_SMEM>>>(qh, ql, kh, kl, vh, vl, oh, ol);

    // output projection
    gemm_mma<<<gemm_grid, 256, GEMM_SMEM>>>(oh, ol, woh, wol, bo, out, nullptr, nullptr, 1.0f, 0);
}

// round 5
// speedup vs baseline: 8.7865x; 2.5693x over previous
#include <cuda_runtime.h>
#include <cuda_fp16.h>
#include <cstdint>

#define D_MODEL 1024
#define N_HEADS 16
#define HEAD_DIM 64
#define BATCH 4
#define SEQ 2048
#define M_TOTAL (BATCH * SEQ)  // 8192

// ---------------------------------------------------------------------------
// Scratch (__device__ globals; no allocation allowed). All fp16.
// ---------------------------------------------------------------------------
__device__ __half g_xq[(size_t)M_TOTAL * D_MODEL];
__device__ __half g_xk[(size_t)M_TOTAL * D_MODEL];
__device__ __half g_xv[(size_t)M_TOTAL * D_MODEL];
__device__ __half g_q[(size_t)M_TOTAL * D_MODEL];   // [B,H,S,D], pre-scaled 0.125
__device__ __half g_k[(size_t)M_TOTAL * D_MODEL];
__device__ __half g_v[(size_t)M_TOTAL * D_MODEL];
__device__ __half g_oa[(size_t)M_TOTAL * D_MODEL];  // attn out [B,S,1024]
__device__ __half s_wq[(size_t)D_MODEL * D_MODEL];
__device__ __half s_wk[(size_t)D_MODEL * D_MODEL];
__device__ __half s_wv[(size_t)D_MODEL * D_MODEL];
__device__ __half s_wo[(size_t)D_MODEL * D_MODEL];

// ---------------------------------------------------------------------------
// PTX helpers (baseline ISA, sm_80-level)
// ---------------------------------------------------------------------------
__device__ __forceinline__ uint32_t smem_to_u32(const void* p) {
    uint32_t a;
    asm("{ .reg .u64 t; cvta.to.shared.u64 t, %1; cvt.u32.u64 %0, t; }" : "=r"(a) : "l"(p));
    return a;
}

#define CP_ASYNC16(dst, src) \
    asm volatile("cp.async.cg.shared.global [%0], [%1], 16;\n" :: "r"(dst), "l"(src))
#define CP_COMMIT() asm volatile("cp.async.commit_group;" ::: "memory")
#define CP_WAIT0()  asm volatile("cp.async.wait_group 0;" ::: "memory")
#define CP_WAIT1()  asm volatile("cp.async.wait_group 1;" ::: "memory")
#define CP_WAIT2()  asm volatile("cp.async.wait_group 2;" ::: "memory")

#define LDSM4(r, a) \
    asm volatile("ldmatrix.sync.aligned.m8n8.x4.shared.b16 {%0,%1,%2,%3}, [%4];" \
        : "=r"((r)[0]), "=r"((r)[1]), "=r"((r)[2]), "=r"((r)[3]) : "r"(a))
#define LDSM4T(r, a) \
    asm volatile("ldmatrix.sync.aligned.m8n8.x4.trans.shared.b16 {%0,%1,%2,%3}, [%4];" \
        : "=r"((r)[0]), "=r"((r)[1]), "=r"((r)[2]), "=r"((r)[3]) : "r"(a))

// d += a * b  (m16n8k16, fp16 in, f32 accum)
#define MMA(d, a, b0v, b1v) \
    asm volatile("mma.sync.aligned.m16n8k16.row.col.f32.f16.f16.f32 " \
        "{%0,%1,%2,%3}, {%4,%5,%6,%7}, {%8,%9}, {%0,%1,%2,%3};" \
        : "+f"((d)[0]), "+f"((d)[1]), "+f"((d)[2]), "+f"((d)[3]) \
        : "r"((a)[0]), "r"((a)[1]), "r"((a)[2]), "r"((a)[3]), \
          "r"(b0v), "r"(b1v))

__device__ __forceinline__ uint32_t pack_h2(float a, float b) {
    __half2 h = __floats2half2_rn(a, b);   // .x = a
    return reinterpret_cast<uint32_t&>(h);
}

// ---------------------------------------------------------------------------
// fp32 -> fp16 convert
// ---------------------------------------------------------------------------
__global__ void __launch_bounds__(256) cvt_h(
    const float4* __restrict__ x, __half2* __restrict__ y, int n4)
{
    int i = blockIdx.x * 256 + threadIdx.x;
    if (i >= n4) return;
    float4 v = x[i];
    y[i * 2 + 0] = __floats2half2_rn(v.x, v.y);
    y[i * 2 + 1] = __floats2half2_rn(v.z, v.w);
}

// ---------------------------------------------------------------------------
// fp16 GEMM core: C[*,1024] = A * B^T + bias.
// CTA 128x128, 8 warps (warp tile 64x32), K-chunk 32, 4-stage cp.async.
// mode 0: fp32 dense out; mode 1: fp16*scale scattered to [B,H,S,D].
// ---------------------------------------------------------------------------
#define ROW_B 80
#define TILE_SM (128 * ROW_B)          // 10240
#define STAGE_SM (2 * TILE_SM)         // 20480 (A, B)
#define NSTAGE 4
#define GEMM_SMEM (NSTAGE * STAGE_SM)  // 81920 -> 2 CTAs/SM
#define NCHUNK 32

__device__ __forceinline__ void g_load_stage(
    uint32_t smem_u, int s, int j, int tid,
    const __half* A, const __half* B, int m0, int n0)
{
    const __half* bases[2] = { A + (size_t)m0 * D_MODEL, B + (size_t)n0 * D_MODEL };
    uint32_t st = smem_u + s * STAGE_SM;
#pragma unroll
    for (int i = 0; i < 4; i++) {
        int idx = i * 256 + tid;      // 0..1023
        int t   = idx >> 9;
        int rem = idx & 511;
        int r   = rem >> 2;           // 0..127
        int sec = rem & 3;            // 16B sector
        const void* src = bases[t] + (size_t)r * D_MODEL + j * 32 + sec * 8;
        CP_ASYNC16(st + t * TILE_SM + r * ROW_B + sec * 16, src);
    }
}

__device__ __forceinline__ void gemm_core(
    const __half* __restrict__ A, const __half* __restrict__ B,
    const float* __restrict__ bias,
    float* __restrict__ Cf, __half* __restrict__ Ch,
    float scale, int mode, char* smem, int m0, int n0)
{
    const uint32_t smem_u = smem_to_u32(smem);
    const int tid  = threadIdx.x;
    const int wid  = tid >> 5;
    const int lane = tid & 31;
    const int wm   = wid >> 2;
    const int wn   = wid & 3;
    const int ldrow = (lane & 7) + ((lane >> 3) & 1) * 8;
    const int ldcol = (lane >> 4) * 16;

    float acc[4][4][4];
#pragma unroll
    for (int i = 0; i < 4; i++)
#pragma unroll
        for (int j = 0; j < 4; j++)
#pragma unroll
            for (int k = 0; k < 4; k++) acc[i][j][k] = 0.f;

#pragma unroll
    for (int s = 0; s < 3; s++) {
        g_load_stage(smem_u, s, s, tid, A, B, m0, n0);
        CP_COMMIT();
    }

    for (int i = 0; i < NCHUNK; i++) {
        if (i < NCHUNK - 2)      { CP_WAIT2(); }
        else if (i == NCHUNK - 2){ CP_WAIT1(); }
        else                     { CP_WAIT0(); }
        __syncthreads();
        if (i + 3 < NCHUNK) {
            g_load_stage(smem_u, (i + 3) % NSTAGE, i + 3, tid, A, B, m0, n0);
            CP_COMMIT();
        }

        const uint32_t base = smem_u + (i % NSTAGE) * STAGE_SM;
        const uint32_t pA = base;
        const uint32_t pB = base + TILE_SM;

#pragma unroll
        for (int ks = 0; ks < 2; ks++) {
            const int kb = ks * 32 + ldcol;
            uint32_t af[4][4];
#pragma unroll
            for (int fm = 0; fm < 4; fm++)
                LDSM4(af[fm], pA + (wm * 64 + fm * 16 + ldrow) * ROW_B + kb);
            uint32_t bf[2][4];
#pragma unroll
            for (int fp = 0; fp < 2; fp++)
                LDSM4(bf[fp], pB + (wn * 32 + fp * 16 + ldrow) * ROW_B + kb);
#pragma unroll
            for (int fm = 0; fm < 4; fm++)
#pragma unroll
                for (int fn = 0; fn < 4; fn++) {
                    const int fp = fn >> 1, sl = fn & 1;
                    MMA(acc[fm][fn], af[fm], bf[fp][sl], bf[fp][sl + 2]);
                }
        }
        __syncthreads();
    }

    const int g = lane >> 2;
    const int ccol = (lane & 3) * 2;
#pragma unroll
    for (int fn = 0; fn < 4; fn++) {
        int col = n0 + wn * 32 + fn * 8 + ccol;
        float b0 = bias[col], b1 = bias[col + 1];
#pragma unroll
        for (int fm = 0; fm < 4; fm++) {
            int mlo = m0 + wm * 64 + fm * 16 + g;
            int mhi = mlo + 8;
            float v0 = acc[fm][fn][0] + b0, v1 = acc[fm][fn][1] + b1;
            float v2 = acc[fm][fn][2] + b0, v3 = acc[fm][fn][3] + b1;
            if (mode == 0) {
                *(float2*)&Cf[(size_t)mlo * D_MODEL + col] = make_float2(v0, v1);
                *(float2*)&Cf[(size_t)mhi * D_MODEL + col] = make_float2(v2, v3);
            } else {
                int h = col >> 6, d = col & 63;
                size_t i0 = (((size_t)((mlo >> 11) * N_HEADS + h) * SEQ) + (mlo & 2047)) * HEAD_DIM + d;
                size_t i1 = (((size_t)((mhi >> 11) * N_HEADS + h) * SEQ) + (mhi & 2047)) * HEAD_DIM + d;
                *(__half2*)&Ch[i0] = __floats2half2_rn(v0 * scale, v1 * scale);
                *(__half2*)&Ch[i1] = __floats2half2_rn(v2 * scale, v3 * scale);
            }
        }
    }
}

// QKV projections fused: grid (8, 64, 3)
__global__ void __launch_bounds__(256, 2) gemm_qkv(
    const __half* __restrict__ xq, const __half* __restrict__ xk, const __half* __restrict__ xv,
    const __half* __restrict__ wq, const __half* __restrict__ wk, const __half* __restrict__ wv,
    const float* __restrict__ bq, const float* __restrict__ bk, const float* __restrict__ bv,
    __half* __restrict__ q, __half* __restrict__ k, __half* __restrict__ v)
{
    extern __shared__ char smem[];
    const __half* A; const __half* B; const float* bi; __half* dst; float sc;
    if (blockIdx.z == 0)      { A = xq; B = wq; bi = bq; dst = q; sc = 0.125f; }
    else if (blockIdx.z == 1) { A = xk; B = wk; bi = bk; dst = k; sc = 1.f; }
    else                      { A = xv; B = wv; bi = bv; dst = v; sc = 1.f; }
    gemm_core(A, B, bi, nullptr, dst, sc, 1, smem, blockIdx.y * 128, blockIdx.x * 128);
}

// Output projection: grid (8, 64)
__global__ void __launch_bounds__(256, 2) gemm_out(
    const __half* __restrict__ A, const __half* __restrict__ B,
    const float* __restrict__ bias, float* __restrict__ Cf)
{
    extern __shared__ char smem[];
    gemm_core(A, B, bias, Cf, nullptr, 1.f, 0, smem, blockIdx.y * 128, blockIdx.x * 128);
}

// ---------------------------------------------------------------------------
// Flash attention on fp16 mma.sync.
// CTA = 128 q rows x one (b,h); 8 warps, warp = 16 q rows x 64-key tile.
// Q pre-scaled by 0.125. Double-buffered K/V via cp.async.
// ---------------------------------------------------------------------------
#define AROW 144                     // 128B data + 16B pad
#define AQ_T (128 * AROW)            // 18432
#define AK_T (64 * AROW)             // 9216
#define AKV_BUF (2 * AK_T)           // 18432 (K, V)
#define ATT_SMEM (AQ_T + 2 * AKV_BUF)  // 55296

__device__ __forceinline__ void a_load_kv(
    uint32_t kvsu, int buf, int tile, int tid, size_t gbase,
    const __half* K, const __half* V)
{
    const __half* srcs[2] = { K + gbase + (size_t)tile * 64 * HEAD_DIM,
                              V + gbase + (size_t)tile * 64 * HEAD_DIM };
    uint32_t dstb = kvsu + buf * AKV_BUF;
#pragma unroll
    for (int it = 0; it < 4; it++) {
        int idx = it * 256 + tid;   // 0..1023
        int t   = idx >> 9;
        int rem = idx & 511;
        int row = rem >> 3;
        int sec = rem & 7;
        CP_ASYNC16(dstb + t * AK_T + row * AROW + sec * 16,
                   srcs[t] + (size_t)row * HEAD_DIM + sec * 8);
    }
}

__global__ void __launch_bounds__(256, 1) attn_mma(
    const __half* __restrict__ Q, const __half* __restrict__ K,
    const __half* __restrict__ V, __half* __restrict__ Oa)
{
    extern __shared__ char smem[];
    const uint32_t su = smem_to_u32(smem);
    const int tid  = threadIdx.x;
    const int wid  = tid >> 5;
    const int lane = tid & 31;
    const int g    = lane >> 2;
    const int bh   = blockIdx.y;
    const int q0   = blockIdx.x * 128;
    const size_t gbase = (size_t)bh * SEQ * HEAD_DIM;
    const int ldrow = (lane & 7) + ((lane >> 3) & 1) * 8;
    const int ldcol = (lane >> 4) * 16;

    // Q tile: 128 rows x 128B
    {
        const __half* qs = Q + gbase + (size_t)q0 * HEAD_DIM;
#pragma unroll
        for (int it = 0; it < 4; it++) {
            int idx = it * 256 + tid;   // 0..1023
            int row = idx >> 3;
            int sec = idx & 7;
            CP_ASYNC16(su + row * AROW + sec * 16,
                       qs + (size_t)row * HEAD_DIM + sec * 8);
        }
    }
    CP_COMMIT();
    const uint32_t kvsu = su + AQ_T;
    a_load_kv(kvsu, 0, 0, tid, gbase, K, V);
    CP_COMMIT();

    CP_WAIT1();   // Q resident
    __syncthreads();

    uint32_t qf[4][4];
    {
        uint32_t qb = su + (wid * 16 + ldrow) * AROW + ldcol;
#pragma unroll
        for (int ks = 0; ks < 4; ks++) LDSM4(qf[ks], qb + ks * 32);
    }

    float O[8][4];
#pragma unroll
    for (int f = 0; f < 8; f++)
#pragma unroll
        for (int k = 0; k < 4; k++) O[f][k] = 0.f;
    float rm0 = -1e30f, rm1 = -1e30f, rl0 = 0.f, rl1 = 0.f;

    for (int t = 0; t < SEQ / 64; t++) {
        CP_WAIT0();
        __syncthreads();
        if (t + 1 < SEQ / 64) {
            a_load_kv(kvsu, (t + 1) & 1, t + 1, tid, gbase, K, V);
            CP_COMMIT();
        }
        const uint32_t kb = kvsu + (t & 1) * AKV_BUF;
        const uint32_t vb = kb + AK_T;

        // S = Q*K^T  (m16 x n64 per warp)
        float S[8][4];
#pragma unroll
        for (int f = 0; f < 8; f++)
#pragma unroll
            for (int k = 0; k < 4; k++) S[f][k] = 0.f;

#pragma unroll
        for (int ks = 0; ks < 4; ks++) {
            const int kc = ks * 32 + ldcol;
            uint32_t kf[4][4];
#pragma unroll
            for (int p = 0; p < 4; p++)
                LDSM4(kf[p], kb + (p * 16 + ldrow) * AROW + kc);
#pragma unroll
            for (int fn = 0; fn < 8; fn++) {
                const int p = fn >> 1, sl = fn & 1;
                MMA(S[fn], qf[ks], kf[p][sl], kf[p][sl + 2]);
            }
        }

        // online softmax (rows g, g+8; quad lanes share rows)
        float mx0 = -1e30f, mx1 = -1e30f;
#pragma unroll
        for (int f = 0; f < 8; f++) {
            mx0 = fmaxf(mx0, fmaxf(S[f][0], S[f][1]));
            mx1 = fmaxf(mx1, fmaxf(S[f][2], S[f][3]));
        }
        mx0 = fmaxf(mx0, __shfl_xor_sync(0xffffffffu, mx0, 1));
        mx0 = fmaxf(mx0, __shfl_xor_sync(0xffffffffu, mx0, 2));
        mx1 = fmaxf(mx1, __shfl_xor_sync(0xffffffffu, mx1, 1));
        mx1 = fmaxf(mx1, __shfl_xor_sync(0xffffffffu, mx1, 2));
        float mn0 = fmaxf(rm0, mx0), mn1 = fmaxf(rm1, mx1);
        float c0 = __expf(rm0 - mn0), c1 = __expf(rm1 - mn1);
        rm0 = mn0; rm1 = mn1;

        float s0 = 0.f, s1 = 0.f;
#pragma unroll
        for (int f = 0; f < 8; f++) {
            S[f][0] = __expf(S[f][0] - mn0); s0 += S[f][0];
            S[f][1] = __expf(S[f][1] - mn0); s0 += S[f][1];
            S[f][2] = __expf(S[f][2] - mn1); s1 += S[f][2];
            S[f][3] = __expf(S[f][3] - mn1); s1 += S[f][3];
        }
        s0 += __shfl_xor_sync(0xffffffffu, s0, 1);
        s0 += __shfl_xor_sync(0xffffffffu, s0, 2);
        s1 += __shfl_xor_sync(0xffffffffu, s1, 1);
        s1 += __shfl_xor_sync(0xffffffffu, s1, 2);
        rl0 = rl0 * c0 + s0;
        rl1 = rl1 * c1 + s1;
#pragma unroll
        for (int f = 0; f < 8; f++) {
            O[f][0] *= c0; O[f][1] *= c0;
            O[f][2] *= c1; O[f][3] *= c1;
        }

        // P -> fp16 A-fragments (k = key dim)
        uint32_t pa[4][4];
#pragma unroll
        for (int kj = 0; kj < 4; kj++) {
            const int f0 = 2 * kj, f1 = f0 + 1;
            pa[kj][0] = pack_h2(S[f0][0], S[f0][1]);
            pa[kj][1] = pack_h2(S[f0][2], S[f0][3]);
            pa[kj][2] = pack_h2(S[f1][0], S[f1][1]);
            pa[kj][3] = pack_h2(S[f1][2], S[f1][3]);
        }

        // O += P*V  (V^T via ldmatrix.trans)
#pragma unroll
        for (int kj = 0; kj < 4; kj++) {
            uint32_t vf[4][4];
#pragma unroll
            for (int p = 0; p < 4; p++)
                LDSM4T(vf[p], vb + (kj * 16 + ldrow) * AROW + p * 32 + ldcol);
#pragma unroll
            for (int fn = 0; fn < 8; fn++) {
                const int p = fn >> 1, sl = (fn & 1) * 2;
                MMA(O[fn], pa[kj], vf[p][sl], vf[p][sl + 1]);
            }
        }
    }

    // epilogue: O/l -> fp16 [B,S,1024]
    const float inv0 = 1.f / rl0, inv1 = 1.f / rl1;
    const int b = bh >> 4;
    const int h = bh & 15;
    const int r0g = q0 + wid * 16 + g;
    const int r1g = r0g + 8;
#pragma unroll
    for (int fn = 0; fn < 8; fn++) {
        int col = h * HEAD_DIM + fn * 8 + (lane & 3) * 2;
        size_t i0 = ((size_t)(b * SEQ + r0g)) * D_MODEL + col;
        size_t i1 = ((size_t)(b * SEQ + r1g)) * D_MODEL + col;
        *(__half2*)&Oa[i0] = __floats2half2_rn(O[fn][0] * inv0, O[fn][1] * inv0);
        *(__half2*)&Oa[i1] = __floats2half2_rn(O[fn][2] * inv1, O[fn][3] * inv1);
    }
}

// ---------------------------------------------------------------------------
extern "C" void kernel_launch(void* const* d_in, const int* in_sizes, int n_in,
                              void* d_out, int out_size)
{
    const float* query = (const float*)d_in[0];
    const float* key   = (const float*)d_in[1];
    const float* value = (const float*)d_in[2];
    const float* bq    = (const float*)d_in[4];
    const float* bk    = (const float*)d_in[6];
    const float* bv    = (const float*)d_in[8];
    const float* bo    = (const float*)d_in[10];
    float* out = (float*)d_out;

    __half *xq, *xk, *xv, *q, *k, *v, *oa, *wq, *wk, *wv, *wo;
    cudaGetSymbolAddress((void**)&xq, g_xq);
    cudaGetSymbolAddress((void**)&xk, g_xk);
    cudaGetSymbolAddress((void**)&xv, g_xv);
    cudaGetSymbolAddress((void**)&q, g_q);
    cudaGetSymbolAddress((void**)&k, g_k);
    cudaGetSymbolAddress((void**)&v, g_v);
    cudaGetSymbolAddress((void**)&oa, g_oa);
    cudaGetSymbolAddress((void**)&wq, s_wq);
    cudaGetSymbolAddress((void**)&wk, s_wk);
    cudaGetSymbolAddress((void**)&wv, s_wv);
    cudaGetSymbolAddress((void**)&wo, s_wo);

    cudaFuncSetAttribute(gemm_qkv, cudaFuncAttributeMaxDynamicSharedMemorySize, GEMM_SMEM);
    cudaFuncSetAttribute(gemm_out, cudaFuncAttributeMaxDynamicSharedMemorySize, GEMM_SMEM);
    cudaFuncSetAttribute(attn_mma, cudaFuncAttributeMaxDynamicSharedMemorySize, ATT_SMEM);

    const int n4_act = M_TOTAL * D_MODEL / 4;
    const int n4_w   = D_MODEL * D_MODEL / 4;
    const int gb_act = (n4_act + 255) / 256;
    const int gb_w   = (n4_w + 255) / 256;

    cvt_h<<<gb_act, 256>>>((const float4*)query, (__half2*)xq, n4_act);
    cvt_h<<<gb_act, 256>>>((const float4*)key,   (__half2*)xk, n4_act);
    cvt_h<<<gb_act, 256>>>((const float4*)value, (__half2*)xv, n4_act);
    cvt_h<<<gb_w, 256>>>((const float4*)d_in[3], (__half2*)wq, n4_w);
    cvt_h<<<gb_w, 256>>>((const float4*)d_in[5], (__half2*)wk, n4_w);
    cvt_h<<<gb_w, 256>>>((const float4*)d_in[7], (__half2*)wv, n4_w);
    cvt_h<<<gb_w, 256>>>((const float4*)d_in[9], (__half2*)wo, n4_w);

    dim3 qkv_grid(D_MODEL / 128, M_TOTAL / 128, 3);  // (8, 64, 3)
    gemm_qkv<<<qkv_grid, 256, GEMM_SMEM>>>(xq, xk, xv, wq, wk, wv, bq, bk, bv, q, k, v);

    dim3 attn_grid(SEQ / 128, BATCH * N_HEADS);  // (16, 64)
    attn_mma<<<attn_grid, 256, ATT_SMEM>>>(q, k, v, oa);

    dim3 out_grid(D_MODEL / 128, M_TOTAL / 128);  // (8, 64)
    gemm_out<<<out_grid, 256, GEMM_SMEM>>>(oa, wo, bo, out);
}

// round 6
// speedup vs baseline: 9.1426x; 1.0405x over previous
#include <cuda_runtime.h>
#include <cuda_fp16.h>
#include <cstdint>

#define D_MODEL 1024
#define N_HEADS 16
#define HEAD_DIM 64
#define BATCH 4
#define SEQ 2048
#define M_TOTAL (BATCH * SEQ)  // 8192

// Q pre-scale: (1/sqrt(64)) * log2(e), so softmax runs in base-2 domain.
#define QSCALE 0.1803368801111204f

// ---------------------------------------------------------------------------
// Scratch (__device__ globals; no allocation allowed). All fp16.
// ---------------------------------------------------------------------------
__device__ __half g_xq[(size_t)M_TOTAL * D_MODEL];
__device__ __half g_xk[(size_t)M_TOTAL * D_MODEL];
__device__ __half g_xv[(size_t)M_TOTAL * D_MODEL];
__device__ __half g_q[(size_t)M_TOTAL * D_MODEL];   // [B,H,S,D], pre-scaled QSCALE
__device__ __half g_k[(size_t)M_TOTAL * D_MODEL];
__device__ __half g_v[(size_t)M_TOTAL * D_MODEL];
__device__ __half g_oa[(size_t)M_TOTAL * D_MODEL];  // attn out [B,S,1024]
__device__ __half s_wq[(size_t)D_MODEL * D_MODEL];
__device__ __half s_wk[(size_t)D_MODEL * D_MODEL];
__device__ __half s_wv[(size_t)D_MODEL * D_MODEL];
__device__ __half s_wo[(size_t)D_MODEL * D_MODEL];

// ---------------------------------------------------------------------------
// PTX helpers (baseline ISA, sm_80-level)
// ---------------------------------------------------------------------------
__device__ __forceinline__ uint32_t smem_to_u32(const void* p) {
    uint32_t a;
    asm("{ .reg .u64 t; cvta.to.shared.u64 t, %1; cvt.u32.u64 %0, t; }" : "=r"(a) : "l"(p));
    return a;
}

#define CP_ASYNC16(dst, src) \
    asm volatile("cp.async.cg.shared.global [%0], [%1], 16;\n" :: "r"(dst), "l"(src))
#define CP_COMMIT() asm volatile("cp.async.commit_group;" ::: "memory")
#define CP_WAIT0()  asm volatile("cp.async.wait_group 0;" ::: "memory")
#define CP_WAIT1()  asm volatile("cp.async.wait_group 1;" ::: "memory")
#define CP_WAIT2()  asm volatile("cp.async.wait_group 2;" ::: "memory")

#define LDSM4(r, a) \
    asm volatile("ldmatrix.sync.aligned.m8n8.x4.shared.b16 {%0,%1,%2,%3}, [%4];" \
        : "=r"((r)[0]), "=r"((r)[1]), "=r"((r)[2]), "=r"((r)[3]) : "r"(a))
#define LDSM4T(r, a) \
    asm volatile("ldmatrix.sync.aligned.m8n8.x4.trans.shared.b16 {%0,%1,%2,%3}, [%4];" \
        : "=r"((r)[0]), "=r"((r)[1]), "=r"((r)[2]), "=r"((r)[3]) : "r"(a))

// d += a * b  (m16n8k16, fp16 in, f32 accum)
#define MMA(d, a, b0v, b1v) \
    asm volatile("mma.sync.aligned.m16n8k16.row.col.f32.f16.f16.f32 " \
        "{%0,%1,%2,%3}, {%4,%5,%6,%7}, {%8,%9}, {%0,%1,%2,%3};" \
        : "+f"((d)[0]), "+f"((d)[1]), "+f"((d)[2]), "+f"((d)[3]) \
        : "r"((a)[0]), "r"((a)[1]), "r"((a)[2]), "r"((a)[3]), \
          "r"(b0v), "r"(b1v))

__device__ __forceinline__ uint32_t pack_h2(float a, float b) {
    __half2 h = __floats2half2_rn(a, b);   // .x = a
    return reinterpret_cast<uint32_t&>(h);
}

// ---------------------------------------------------------------------------
// fp32 -> fp16 converts, fused over grid.z
// ---------------------------------------------------------------------------
__global__ void __launch_bounds__(256) cvt_act(
    const float4* __restrict__ x0, const float4* __restrict__ x1,
    const float4* __restrict__ x2,
    __half2* __restrict__ y0, __half2* __restrict__ y1, __half2* __restrict__ y2,
    int n4)
{
    const float4* x = (blockIdx.z == 0) ? x0 : (blockIdx.z == 1) ? x1 : x2;
    __half2*      y = (blockIdx.z == 0) ? y0 : (blockIdx.z == 1) ? y1 : y2;
    int i = blockIdx.x * 256 + threadIdx.x;
    if (i >= n4) return;
    float4 v = x[i];
    y[i * 2 + 0] = __floats2half2_rn(v.x, v.y);
    y[i * 2 + 1] = __floats2half2_rn(v.z, v.w);
}

__global__ void __launch_bounds__(256) cvt_w(
    const float4* __restrict__ x0, const float4* __restrict__ x1,
    const float4* __restrict__ x2, const float4* __restrict__ x3,
    __half2* __restrict__ y0, __half2* __restrict__ y1,
    __half2* __restrict__ y2, __half2* __restrict__ y3,
    int n4)
{
    const float4* x = (blockIdx.z == 0) ? x0 : (blockIdx.z == 1) ? x1
                    : (blockIdx.z == 2) ? x2 : x3;
    __half2*      y = (blockIdx.z == 0) ? y0 : (blockIdx.z == 1) ? y1
                    : (blockIdx.z == 2) ? y2 : y3;
    int i = blockIdx.x * 256 + threadIdx.x;
    if (i >= n4) return;
    float4 v = x[i];
    y[i * 2 + 0] = __floats2half2_rn(v.x, v.y);
    y[i * 2 + 1] = __floats2half2_rn(v.z, v.w);
}

// ---------------------------------------------------------------------------
// fp16 GEMM core: C[*,1024] = A * B^T + bias.
// CTA 128x128, 8 warps (warp tile 64x32), K-chunk 32, 4-stage cp.async.
// ---------------------------------------------------------------------------
#define ROW_B 80
#define TILE_SM (128 * ROW_B)          // 10240
#define STAGE_SM (2 * TILE_SM)         // 20480 (A, B)
#define NSTAGE 4
#define GEMM_SMEM (NSTAGE * STAGE_SM)  // 81920 -> 2 CTAs/SM
#define NCHUNK 32

__device__ __forceinline__ void g_load_stage(
    uint32_t smem_u, int s, int j, int tid,
    const __half* A, const __half* B, int m0, int n0)
{
    const __half* bases[2] = { A + (size_t)m0 * D_MODEL, B + (size_t)n0 * D_MODEL };
    uint32_t st = smem_u + s * STAGE_SM;
#pragma unroll
    for (int i = 0; i < 4; i++) {
        int idx = i * 256 + tid;      // 0..1023
        int t   = idx >> 9;
        int rem = idx & 511;
        int r   = rem >> 2;           // 0..127
        int sec = rem & 3;            // 16B sector
        const void* src = bases[t] + (size_t)r * D_MODEL + j * 32 + sec * 8;
        CP_ASYNC16(st + t * TILE_SM + r * ROW_B + sec * 16, src);
    }
}

__device__ __forceinline__ void gemm_core(
    const __half* __restrict__ A, const __half* __restrict__ B,
    const float* __restrict__ bias,
    float* __restrict__ Cf, __half* __restrict__ Ch,
    float scale, int mode, char* smem, int m0, int n0)
{
    const uint32_t smem_u = smem_to_u32(smem);
    const int tid  = threadIdx.x;
    const int wid  = tid >> 5;
    const int lane = tid & 31;
    const int wm   = wid >> 2;
    const int wn   = wid & 3;
    const int ldrow = (lane & 7) + ((lane >> 3) & 1) * 8;
    const int ldcol = (lane >> 4) * 16;

    float acc[4][4][4];
#pragma unroll
    for (int i = 0; i < 4; i++)
#pragma unroll
        for (int j = 0; j < 4; j++)
#pragma unroll
            for (int k = 0; k < 4; k++) acc[i][j][k] = 0.f;

#pragma unroll
    for (int s = 0; s < 3; s++) {
        g_load_stage(smem_u, s, s, tid, A, B, m0, n0);
        CP_COMMIT();
    }

    for (int i = 0; i < NCHUNK; i++) {
        if (i < NCHUNK - 2)      { CP_WAIT2(); }
        else if (i == NCHUNK - 2){ CP_WAIT1(); }
        else                     { CP_WAIT0(); }
        __syncthreads();
        if (i + 3 < NCHUNK) {
            g_load_stage(smem_u, (i + 3) % NSTAGE, i + 3, tid, A, B, m0, n0);
            CP_COMMIT();
        }

        const uint32_t base = smem_u + (i % NSTAGE) * STAGE_SM;
        const uint32_t pA = base;
        const uint32_t pB = base + TILE_SM;

#pragma unroll
        for (int ks = 0; ks < 2; ks++) {
            const int kb = ks * 32 + ldcol;
            uint32_t af[4][4];
#pragma unroll
            for (int fm = 0; fm < 4; fm++)
                LDSM4(af[fm], pA + (wm * 64 + fm * 16 + ldrow) * ROW_B + kb);
            uint32_t bf[2][4];
#pragma unroll
            for (int fp = 0; fp < 2; fp++)
                LDSM4(bf[fp], pB + (wn * 32 + fp * 16 + ldrow) * ROW_B + kb);
#pragma unroll
            for (int fm = 0; fm < 4; fm++)
#pragma unroll
                for (int fn = 0; fn < 4; fn++) {
                    const int fp = fn >> 1, sl = fn & 1;
                    MMA(acc[fm][fn], af[fm], bf[fp][sl], bf[fp][sl + 2]);
                }
        }
        __syncthreads();
    }

    const int g = lane >> 2;
    const int ccol = (lane & 3) * 2;
#pragma unroll
    for (int fn = 0; fn < 4; fn++) {
        int col = n0 + wn * 32 + fn * 8 + ccol;
        float b0 = bias[col], b1 = bias[col + 1];
#pragma unroll
        for (int fm = 0; fm < 4; fm++) {
            int mlo = m0 + wm * 64 + fm * 16 + g;
            int mhi = mlo + 8;
            float v0 = acc[fm][fn][0] + b0, v1 = acc[fm][fn][1] + b1;
            float v2 = acc[fm][fn][2] + b0, v3 = acc[fm][fn][3] + b1;
            if (mode == 0) {
                *(float2*)&Cf[(size_t)mlo * D_MODEL + col] = make_float2(v0, v1);
                *(float2*)&Cf[(size_t)mhi * D_MODEL + col] = make_float2(v2, v3);
            } else {
                int h = col >> 6, d = col & 63;
                size_t i0 = (((size_t)((mlo >> 11) * N_HEADS + h) * SEQ) + (mlo & 2047)) * HEAD_DIM + d;
                size_t i1 = (((size_t)((mhi >> 11) * N_HEADS + h) * SEQ) + (mhi & 2047)) * HEAD_DIM + d;
                *(__half2*)&Ch[i0] = __floats2half2_rn(v0 * scale, v1 * scale);
                *(__half2*)&Ch[i1] = __floats2half2_rn(v2 * scale, v3 * scale);
            }
        }
    }
}

// QKV projections fused: grid (8, 64, 3)
__global__ void __launch_bounds__(256, 2) gemm_qkv(
    const __half* __restrict__ xq, const __half* __restrict__ xk, const __half* __restrict__ xv,
    const __half* __restrict__ wq, const __half* __restrict__ wk, const __half* __restrict__ wv,
    const float* __restrict__ bq, const float* __restrict__ bk, const float* __restrict__ bv,
    __half* __restrict__ q, __half* __restrict__ k, __half* __restrict__ v)
{
    extern __shared__ char smem[];
    const __half* A; const __half* B; const float* bi; __half* dst; float sc;
    if (blockIdx.z == 0)      { A = xq; B = wq; bi = bq; dst = q; sc = QSCALE; }
    else if (blockIdx.z == 1) { A = xk; B = wk; bi = bk; dst = k; sc = 1.f; }
    else                      { A = xv; B = wv; bi = bv; dst = v; sc = 1.f; }
    gemm_core(A, B, bi, nullptr, dst, sc, 1, smem, blockIdx.y * 128, blockIdx.x * 128);
}

// Output projection: grid (8, 64)
__global__ void __launch_bounds__(256, 2) gemm_out(
    const __half* __restrict__ A, const __half* __restrict__ B,
    const float* __restrict__ bias, float* __restrict__ Cf)
{
    extern __shared__ char smem[];
    gemm_core(A, B, bias, Cf, nullptr, 1.f, 0, smem, blockIdx.y * 128, blockIdx.x * 128);
}

// ---------------------------------------------------------------------------
// Flash attention on fp16 mma.sync (base-2 softmax; Q pre-scaled by QSCALE).
// CTA = 128 q rows x one (b,h); 8 warps, warp = 16 q rows x 64-key tile.
// 2 CTAs/SM target.
// ---------------------------------------------------------------------------
#define AROW 144                     // 128B data + 16B pad
#define AQ_T (128 * AROW)            // 18432
#define AK_T (64 * AROW)             // 9216
#define AKV_BUF (2 * AK_T)           // 18432 (K, V)
#define ATT_SMEM (AQ_T + 2 * AKV_BUF)  // 55296 -> 2 CTAs/SM

__device__ __forceinline__ void a_load_kv(
    uint32_t kvsu, int buf, int tile, int tid, size_t gbase,
    const __half* K, const __half* V)
{
    const __half* srcs[2] = { K + gbase + (size_t)tile * 64 * HEAD_DIM,
                              V + gbase + (size_t)tile * 64 * HEAD_DIM };
    uint32_t dstb = kvsu + buf * AKV_BUF;
#pragma unroll
    for (int it = 0; it < 4; it++) {
        int idx = it * 256 + tid;   // 0..1023
        int t   = idx >> 9;
        int rem = idx & 511;
        int row = rem >> 3;
        int sec = rem & 7;
        CP_ASYNC16(dstb + t * AK_T + row * AROW + sec * 16,
                   srcs[t] + (size_t)row * HEAD_DIM + sec * 8);
    }
}

__global__ void __launch_bounds__(256, 2) attn_mma(
    const __half* __restrict__ Q, const __half* __restrict__ K,
    const __half* __restrict__ V, __half* __restrict__ Oa)
{
    extern __shared__ char smem[];
    const uint32_t su = smem_to_u32(smem);
    const int tid  = threadIdx.x;
    const int wid  = tid >> 5;
    const int lane = tid & 31;
    const int g    = lane >> 2;
    const int bh   = blockIdx.y;
    const int q0   = blockIdx.x * 128;
    const size_t gbase = (size_t)bh * SEQ * HEAD_DIM;
    const int ldrow = (lane & 7) + ((lane >> 3) & 1) * 8;
    const int ldcol = (lane >> 4) * 16;

    // Q tile: 128 rows x 128B
    {
        const __half* qs = Q + gbase + (size_t)q0 * HEAD_DIM;
#pragma unroll
        for (int it = 0; it < 4; it++) {
            int idx = it * 256 + tid;   // 0..1023
            int row = idx >> 3;
            int sec = idx & 7;
            CP_ASYNC16(su + row * AROW + sec * 16,
                       qs + (size_t)row * HEAD_DIM + sec * 8);
        }
    }
    CP_COMMIT();
    const uint32_t kvsu = su + AQ_T;
    a_load_kv(kvsu, 0, 0, tid, gbase, K, V);
    CP_COMMIT();

    CP_WAIT1();   // Q resident
    __syncthreads();

    uint32_t qf[4][4];
    {
        uint32_t qb = su + (wid * 16 + ldrow) * AROW + ldcol;
#pragma unroll
        for (int ks = 0; ks < 4; ks++) LDSM4(qf[ks], qb + ks * 32);
    }

    float O[8][4];
#pragma unroll
    for (int f = 0; f < 8; f++)
#pragma unroll
        for (int k = 0; k < 4; k++) O[f][k] = 0.f;
    float rm0 = -1e30f, rm1 = -1e30f, rl0 = 0.f, rl1 = 0.f;

    for (int t = 0; t < SEQ / 64; t++) {
        CP_WAIT0();
        __syncthreads();
        if (t + 1 < SEQ / 64) {
            a_load_kv(kvsu, (t + 1) & 1, t + 1, tid, gbase, K, V);
            CP_COMMIT();
        }
        const uint32_t kb = kvsu + (t & 1) * AKV_BUF;
        const uint32_t vb = kb + AK_T;

        // S = Q*K^T  (m16 x n64 per warp), S in log2 domain
        float S[8][4];
#pragma unroll
        for (int f = 0; f < 8; f++)
#pragma unroll
            for (int k = 0; k < 4; k++) S[f][k] = 0.f;

#pragma unroll
        for (int ks = 0; ks < 4; ks++) {
            const int kc = ks * 32 + ldcol;
            uint32_t kf[4][4];
#pragma unroll
            for (int p = 0; p < 4; p++)
                LDSM4(kf[p], kb + (p * 16 + ldrow) * AROW + kc);
#pragma unroll
            for (int fn = 0; fn < 8; fn++) {
                const int p = fn >> 1, sl = fn & 1;
                MMA(S[fn], qf[ks], kf[p][sl], kf[p][sl + 2]);
            }
        }

        // online softmax, base 2 (rows g, g+8; quad lanes share rows)
        float mx0 = -1e30f, mx1 = -1e30f;
#pragma unroll
        for (int f = 0; f < 8; f++) {
            mx0 = fmaxf(mx0, fmaxf(S[f][0], S[f][1]));
            mx1 = fmaxf(mx1, fmaxf(S[f][2], S[f][3]));
        }
        mx0 = fmaxf(mx0, __shfl_xor_sync(0xffffffffu, mx0, 1));
        mx0 = fmaxf(mx0, __shfl_xor_sync(0xffffffffu, mx0, 2));
        mx1 = fmaxf(mx1, __shfl_xor_sync(0xffffffffu, mx1, 1));
        mx1 = fmaxf(mx1, __shfl_xor_sync(0xffffffffu, mx1, 2));
        float mn0 = fmaxf(rm0, mx0), mn1 = fmaxf(rm1, mx1);
        float c0 = exp2f(rm0 - mn0), c1 = exp2f(rm1 - mn1);
        rm0 = mn0; rm1 = mn1;

        float s0 = 0.f, s1 = 0.f;
#pragma unroll
        for (int f = 0; f < 8; f++) {
            S[f][0] = exp2f(S[f][0] - mn0); s0 += S[f][0];
            S[f][1] = exp2f(S[f][1] - mn0); s0 += S[f][1];
            S[f][2] = exp2f(S[f][2] - mn1); s1 += S[f][2];
            S[f][3] = exp2f(S[f][3] - mn1); s1 += S[f][3];
        }
        s0 += __shfl_xor_sync(0xffffffffu, s0, 1);
        s0 += __shfl_xor_sync(0xffffffffu, s0, 2);
        s1 += __shfl_xor_sync(0xffffffffu, s1, 1);
        s1 += __shfl_xor_sync(0xffffffffu, s1, 2);
        rl0 = rl0 * c0 + s0;
        rl1 = rl1 * c1 + s1;
#pragma unroll
        for (int f = 0; f < 8; f++) {
            O[f][0] *= c0; O[f][1] *= c0;
            O[f][2] *= c1; O[f][3] *= c1;
        }

        // P -> fp16 A-fragments (k = key dim)
        uint32_t pa[4][4];
#pragma unroll
        for (int kj = 0; kj < 4; kj++) {
            const int f0 = 2 * kj, f1 = f0 + 1;
            pa[kj][0] = pack_h2(S[f0][0], S[f0][1]);
            pa[kj][1] = pack_h2(S[f0][2], S[f0][3]);
            pa[kj][2] = pack_h2(S[f1][0], S[f1][1]);
            pa[kj][3] = pack_h2(S[f1][2], S[f1][3]);
        }

        // O += P*V  (V^T via ldmatrix.trans)
#pragma unroll
        for (int kj = 0; kj < 4; kj++) {
            uint32_t vf[4][4];
#pragma unroll
            for (int p = 0; p < 4; p++)
                LDSM4T(vf[p], vb + (kj * 16 + ldrow) * AROW + p * 32 + ldcol);
#pragma unroll
            for (int fn = 0; fn < 8; fn++) {
                const int p = fn >> 1, sl = (fn & 1) * 2;
                MMA(O[fn], pa[kj], vf[p][sl], vf[p][sl + 1]);
            }
        }
    }

    // epilogue: O/l -> fp16 [B,S,1024]
    const float inv0 = 1.f / rl0, inv1 = 1.f / rl1;
    const int b = bh >> 4;
    const int h = bh & 15;
    const int r0g = q0 + wid * 16 + g;
    const int r1g = r0g + 8;
#pragma unroll
    for (int fn = 0; fn < 8; fn++) {
        int col = h * HEAD_DIM + fn * 8 + (lane & 3) * 2;
        size_t i0 = ((size_t)(b * SEQ + r0g)) * D_MODEL + col;
        size_t i1 = ((size_t)(b * SEQ + r1g)) * D_MODEL + col;
        *(__half2*)&Oa[i0] = __floats2half2_rn(O[fn][0] * inv0, O[fn][1] * inv0);
        *(__half2*)&Oa[i1] = __floats2half2_rn(O[fn][2] * inv1, O[fn][3] * inv1);
    }
}

// ---------------------------------------------------------------------------
extern "C" void kernel_launch(void* const* d_in, const int* in_sizes, int n_in,
                              void* d_out, int out_size)
{
    const float* query = (const float*)d_in[0];
    const float* key   = (const float*)d_in[1];
    const float* value = (const float*)d_in[2];
    const float* bq    = (const float*)d_in[4];
    const float* bk    = (const float*)d_in[6];
    const float* bv    = (const float*)d_in[8];
    const float* bo    = (const float*)d_in[10];
    float* out = (float*)d_out;

    __half *xq, *xk, *xv, *q, *k, *v, *oa, *wq, *wk, *wv, *wo;
    cudaGetSymbolAddress((void**)&xq, g_xq);
    cudaGetSymbolAddress((void**)&xk, g_xk);
    cudaGetSymbolAddress((void**)&xv, g_xv);
    cudaGetSymbolAddress((void**)&q, g_q);
    cudaGetSymbolAddress((void**)&k, g_k);
    cudaGetSymbolAddress((void**)&v, g_v);
    cudaGetSymbolAddress((void**)&oa, g_oa);
    cudaGetSymbolAddress((void**)&wq, s_wq);
    cudaGetSymbolAddress((void**)&wk, s_wk);
    cudaGetSymbolAddress((void**)&wv, s_wv);
    cudaGetSymbolAddress((void**)&wo, s_wo);

    cudaFuncSetAttribute(gemm_qkv, cudaFuncAttributeMaxDynamicSharedMemorySize, GEMM_SMEM);
    cudaFuncSetAttribute(gemm_out, cudaFuncAttributeMaxDynamicSharedMemorySize, GEMM_SMEM);
    cudaFuncSetAttribute(attn_mma, cudaFuncAttributeMaxDynamicSharedMemorySize, ATT_SMEM);

    const int n4_act = M_TOTAL * D_MODEL / 4;   // 2,097,152
    const int n4_w   = D_MODEL * D_MODEL / 4;   // 262,144
    const int gb_act = (n4_act + 255) / 256;
    const int gb_w   = (n4_w + 255) / 256;

    dim3 cvt_act_grid(gb_act, 1, 3);
    cvt_act<<<cvt_act_grid, 256>>>((const float4*)query, (const float4*)key,
                                   (const float4*)value,
                                   (__half2*)xq, (__half2*)xk, (__half2*)xv, n4_act);
    dim3 cvt_w_grid(gb_w, 1, 4);
    cvt_w<<<cvt_w_grid, 256>>>((const float4*)d_in[3], (const float4*)d_in[5],
                               (const float4*)d_in[7], (const float4*)d_in[9],
                               (__half2*)wq, (__half2*)wk, (__half2*)wv, (__half2*)wo, n4_w);

    dim3 qkv_grid(D_MODEL / 128, M_TOTAL / 128, 3);  // (8, 64, 3)
    gemm_qkv<<<qkv_grid, 256, GEMM_SMEM>>>(xq, xk, xv, wq, wk, wv, bq, bk, bv, q, k, v);

    dim3 attn_grid(SEQ / 128, BATCH * N_HEADS);  // (16, 64)
    attn_mma<<<attn_grid, 256, ATT_SMEM>>>(q, k, v, oa);

    dim3 out_grid(D_MODEL / 128, M_TOTAL / 128);  // (8, 64)
    gemm_out<<<out_grid, 256, GEMM_SMEM>>>(oa, wo, bo, out);
}